// round 9
// baseline (speedup 1.0000x reference)
#include <cuda_runtime.h>
#include <cuda_fp16.h>
#include <math.h>
#include <stdint.h>

#define NTOK 8192
#define DIM  512

// ------------------------- scratch (__device__ globals) -------------------------
__device__ __align__(256) __half g_xh [(size_t)NTOK * DIM];
__device__ __align__(256) __half g_wqT[(size_t)DIM * DIM];
__device__ __align__(256) __half g_wkT[(size_t)DIM * DIM];
__device__ __align__(256) __half g_wvT[(size_t)DIM * DIM];
__device__ __align__(256) __half g_woT[(size_t)DIM * DIM];
__device__ __align__(256) __half g_q  [(size_t)NTOK * DIM];
__device__ __align__(256) __half g_k  [(size_t)NTOK * DIM];
__device__ __align__(256) __half g_vT [(size_t)DIM * NTOK];
__device__ __align__(256) __half g_t  [(size_t)NTOK * DIM];
__device__ __align__(256) __half g_s  [(size_t)NTOK * NTOK];   // 128 MB scores/attn

// ------------------------- helpers -------------------------
__device__ __forceinline__ uint32_t smem_u32(const void* p) {
    uint32_t a;
    asm("{ .reg .u64 t; cvta.to.shared.u64 t, %1; cvt.u32.u64 %0, t; }" : "=r"(a) : "l"(p));
    return a;
}

__device__ __forceinline__ void mma_f16(float* d, const uint32_t* a, const uint32_t* b) {
    asm volatile(
        "mma.sync.aligned.m16n8k16.row.col.f32.f16.f16.f32 "
        "{%0,%1,%2,%3}, {%4,%5,%6,%7}, {%8,%9}, {%0,%1,%2,%3};"
        : "+f"(d[0]), "+f"(d[1]), "+f"(d[2]), "+f"(d[3])
        : "r"(a[0]), "r"(a[1]), "r"(a[2]), "r"(a[3]),
          "r"(b[0]), "r"(b[1]));
}

__device__ __forceinline__ void cph16(uint32_t dst, const __half* src) {
    asm volatile("cp.async.cg.shared.global [%0], [%1], 16;\n" :: "r"(dst), "l"(src));
}

__device__ __forceinline__ void store2(__half* C, size_t off, float a, float b) {
    *reinterpret_cast<__half2*>(C + off) = __floats2half2_rn(a, b);
}
__device__ __forceinline__ void store2(float* C, size_t off, float a, float b) {
    *reinterpret_cast<float2*>(C + off) = make_float2(a, b);
}

// ============================================================================
// Kernel 1: 128x128 tile GEMM (2 CTAs/SM) — for small-N GEMMs (QKV, out proj)
// ============================================================================
#define BM 128
#define BN 128
#define STAGE_BYTES (BM * 128 + BN * 128)     // 32768
#define NSTAGE 3
#define SMEM_BYTES  (NSTAGE * STAGE_BYTES + 128)

__device__ __forceinline__ void load_stage_h(const __half* __restrict__ Ag,
                                             const __half* __restrict__ Bg,
                                             int K, uint32_t Ab, uint32_t Bb, int tid)
{
#pragma unroll
    for (int i = 0; i < 4; i++) {
        int c = tid + i * 256;
        int m = c >> 3, ko = c & 7;
        cph16(Ab + m * 128 + ((ko ^ (m & 7)) << 4), Ag + (size_t)m * K + ko * 8);
    }
#pragma unroll
    for (int i = 0; i < 4; i++) {
        int c = tid + i * 256;
        int m = c >> 3, ko = c & 7;
        cph16(Bb + m * 128 + ((ko ^ (m & 7)) << 4), Bg + (size_t)m * K + ko * 8);
    }
    asm volatile("cp.async.commit_group;" ::: "memory");
}

template <typename OutT>
__device__ __forceinline__ void hgemm_core(
    const __half* __restrict__ A, const __half* __restrict__ Bt,
    const float* __restrict__ bias, OutT* __restrict__ C,
    int M, int N, int K, float alpha, bool rowbias,
    int bx, int by, uint32_t sb, int tid)
{
    const int lid = tid & 31;
    const int wid = tid >> 5;
    const int grp = lid >> 2;
    const int tig = lid & 3;
    const int m0  = (wid >> 2) * 64;
    const int n0  = (wid & 3) * 32;
    const int row0 = by * BM;
    const int col0 = bx * BN;
    const int KT = K >> 6;

    const int rrA  = (lid & 7) + ((lid >> 3) & 1) * 8;
    const int selA = (lid >> 4) & 1;
    const int rnB  = lid & 7;
    const int selB = (lid >> 3) & 1;

    float acc[4][4][4];
#pragma unroll
    for (int i = 0; i < 4; i++)
#pragma unroll
        for (int j = 0; j < 4; j++)
#pragma unroll
            for (int e = 0; e < 4; e++) acc[i][j][e] = 0.0f;

    const __half* Arow = A  + (size_t)row0 * K;
    const __half* Brow = Bt + (size_t)col0 * K;

    load_stage_h(Arow, Brow, K, sb, sb + BM * 128, tid);
    if (KT > 1) {
        uint32_t s1 = sb + STAGE_BYTES;
        load_stage_h(Arow + 64, Brow + 64, K, s1, s1 + BM * 128, tid);
    }

    int stage = 0;
    for (int kt = 0; kt < KT; kt++) {
        if (kt + 1 < KT) asm volatile("cp.async.wait_group 1;" ::: "memory");
        else             asm volatile("cp.async.wait_group 0;" ::: "memory");
        __syncthreads();

        if (kt + 2 < KT) {
            int ls = (stage + 2) % NSTAGE;
            uint32_t Ab2 = sb + ls * STAGE_BYTES;
            load_stage_h(Arow + (kt + 2) * 64, Brow + (kt + 2) * 64, K,
                         Ab2, Ab2 + BM * 128, tid);
        }

        const uint32_t Ab = sb + stage * STAGE_BYTES;
        const uint32_t Bb = Ab + BM * 128;

#pragma unroll
        for (int kk = 0; kk < 4; kk++) {
            uint32_t af[4][4];
#pragma unroll
            for (int i = 0; i < 4; i++) {
                int m = m0 + i * 16 + rrA;
                uint32_t adr = Ab + m * 128 + (((kk * 2 + selA) ^ (m & 7)) << 4);
                asm volatile("ldmatrix.sync.aligned.m8n8.x4.shared.b16 {%0,%1,%2,%3}, [%4];"
                    : "=r"(af[i][0]), "=r"(af[i][1]), "=r"(af[i][2]), "=r"(af[i][3])
                    : "r"(adr));
            }
            uint32_t bf[4][2];
#pragma unroll
            for (int j = 0; j < 4; j++) {
                int n = n0 + j * 8 + rnB;
                uint32_t adr = Bb + n * 128 + (((kk * 2 + selB) ^ (n & 7)) << 4);
                asm volatile("ldmatrix.sync.aligned.m8n8.x2.shared.b16 {%0,%1}, [%2];"
                    : "=r"(bf[j][0]), "=r"(bf[j][1])
                    : "r"(adr));
            }
#pragma unroll
            for (int i = 0; i < 4; i++)
#pragma unroll
                for (int j = 0; j < 4; j++)
                    mma_f16(acc[i][j], af[i], bf[j]);
        }
        stage = (stage + 1) % NSTAGE;
    }

#pragma unroll
    for (int j = 0; j < 4; j++) {
        int col = col0 + n0 + j * 8 + tig * 2;
        float cb0 = 0.0f, cb1 = 0.0f;
        if (bias && !rowbias) { cb0 = bias[col]; cb1 = bias[col + 1]; }
#pragma unroll
        for (int i = 0; i < 4; i++) {
            int r = row0 + m0 + i * 16 + grp;
            float rb0 = 0.0f, rb8 = 0.0f;
            if (bias && rowbias) { rb0 = bias[r]; rb8 = bias[r + 8]; }
            float f0 = alpha * acc[i][j][0] + cb0 + rb0;
            float f1 = alpha * acc[i][j][1] + cb1 + rb0;
            float f2 = alpha * acc[i][j][2] + cb0 + rb8;
            float f3 = alpha * acc[i][j][3] + cb1 + rb8;
            store2(C, (size_t)r * N + col, f0, f1);
            store2(C, (size_t)(r + 8) * N + col, f2, f3);
        }
    }
}

template <typename OutT>
__global__ void __launch_bounds__(256, 2)
hgemm(const __half* __restrict__ A, const __half* __restrict__ Bt,
      const float* __restrict__ bias, OutT* __restrict__ C,
      int M, int N, int K, float alpha)
{
    extern __shared__ char smraw[];
    uint32_t sb = (smem_u32(smraw) + 127u) & ~127u;
    hgemm_core<OutT>(A, Bt, bias, C, M, N, K, alpha, false,
                     blockIdx.x, blockIdx.y, sb, threadIdx.x);
}

__global__ void __launch_bounds__(256, 2)
qkv_fused(const __half* __restrict__ xh,
          const __half* __restrict__ wqT, const __half* __restrict__ wkT,
          const __half* __restrict__ wvT,
          const float* __restrict__ bq, const float* __restrict__ bk,
          const float* __restrict__ bv,
          __half* __restrict__ q, __half* __restrict__ k, __half* __restrict__ vT)
{
    extern __shared__ char smraw[];
    uint32_t sb = (smem_u32(smraw) + 127u) & ~127u;
    const int z = blockIdx.z;
    if (z < 2) {
        hgemm_core<__half>(xh, z ? wkT : wqT, z ? bk : bq, z ? k : q,
                           NTOK, DIM, DIM, 1.0f, false,
                           blockIdx.x, blockIdx.y, sb, threadIdx.x);
    } else {
        hgemm_core<__half>(wvT, xh, bv, vT,
                           DIM, NTOK, DIM, 1.0f, true,
                           blockIdx.y, blockIdx.x, sb, threadIdx.x);
    }
}

// ============================================================================
// Kernel 2: 128x256 tile, 64x64 warp tile (1 CTA/SM) — big GEMMs
// ============================================================================
#define WBM 128
#define WBN 256
#define WSTAGE_BYTES (WBM * 128 + WBN * 128)      // 49152
#define WNSTAGE 3
#define WSMEM_BYTES  (WNSTAGE * WSTAGE_BYTES + 128)

__device__ __forceinline__ void load_stage_w(const __half* __restrict__ Ag,
                                             const __half* __restrict__ Bg,
                                             int K, uint32_t Ab, uint32_t Bb, int tid)
{
#pragma unroll
    for (int i = 0; i < 4; i++) {                  // A: 128 rows * 8 chunks
        int c = tid + i * 256;
        int m = c >> 3, ko = c & 7;
        cph16(Ab + m * 128 + ((ko ^ (m & 7)) << 4), Ag + (size_t)m * K + ko * 8);
    }
#pragma unroll
    for (int i = 0; i < 8; i++) {                  // B: 256 rows * 8 chunks
        int c = tid + i * 256;
        int m = c >> 3, ko = c & 7;
        cph16(Bb + m * 128 + ((ko ^ (m & 7)) << 4), Bg + (size_t)m * K + ko * 8);
    }
    asm volatile("cp.async.commit_group;" ::: "memory");
}

template <typename OutT>
__global__ void __launch_bounds__(256, 1)
hgemm_wide(const __half* __restrict__ A, const __half* __restrict__ Bt,
           OutT* __restrict__ C, int M, int N, int K, float alpha)
{
    extern __shared__ char smraw[];
    const uint32_t sb = (smem_u32(smraw) + 127u) & ~127u;
    const int tid = threadIdx.x;
    const int lid = tid & 31;
    const int wid = tid >> 5;
    const int grp = lid >> 2;
    const int tig = lid & 3;
    const int m0  = (wid >> 2) * 64;          // 2 warp rows
    const int n0  = (wid & 3) * 64;           // 4 warp cols
    const int row0 = blockIdx.y * WBM;
    const int col0 = blockIdx.x * WBN;
    const int KT = K >> 6;

    const int rrA  = (lid & 7) + ((lid >> 3) & 1) * 8;
    const int selA = (lid >> 4) & 1;
    // B x4: rows n..n+7 (lanes 0-15), n+8..n+15 (lanes 16-31); chunk = (lid>>3)&1
    const int rnBW = (lid & 7) + ((lid >> 4) & 1) * 8;
    const int selB = (lid >> 3) & 1;

    float acc[4][8][4];
#pragma unroll
    for (int i = 0; i < 4; i++)
#pragma unroll
        for (int j = 0; j < 8; j++)
#pragma unroll
            for (int e = 0; e < 4; e++) acc[i][j][e] = 0.0f;

    const __half* Arow = A  + (size_t)row0 * K;
    const __half* Brow = Bt + (size_t)col0 * K;

    load_stage_w(Arow, Brow, K, sb, sb + WBM * 128, tid);
    if (KT > 1) {
        uint32_t s1 = sb + WSTAGE_BYTES;
        load_stage_w(Arow + 64, Brow + 64, K, s1, s1 + WBM * 128, tid);
    }

    int stage = 0;
    for (int kt = 0; kt < KT; kt++) {
        if (kt + 1 < KT) asm volatile("cp.async.wait_group 1;" ::: "memory");
        else             asm volatile("cp.async.wait_group 0;" ::: "memory");
        __syncthreads();

        if (kt + 2 < KT) {
            int ls = (stage + 2) % WNSTAGE;
            uint32_t Ab2 = sb + ls * WSTAGE_BYTES;
            load_stage_w(Arow + (kt + 2) * 64, Brow + (kt + 2) * 64, K,
                         Ab2, Ab2 + WBM * 128, tid);
        }

        const uint32_t Ab = sb + stage * WSTAGE_BYTES;
        const uint32_t Bb = Ab + WBM * 128;

#pragma unroll
        for (int kk = 0; kk < 4; kk++) {
            uint32_t af[4][4];
#pragma unroll
            for (int i = 0; i < 4; i++) {
                int m = m0 + i * 16 + rrA;
                uint32_t adr = Ab + m * 128 + (((kk * 2 + selA) ^ (m & 7)) << 4);
                asm volatile("ldmatrix.sync.aligned.m8n8.x4.shared.b16 {%0,%1,%2,%3}, [%4];"
                    : "=r"(af[i][0]), "=r"(af[i][1]), "=r"(af[i][2]), "=r"(af[i][3])
                    : "r"(adr));
            }
            uint32_t bf[4][4];   // bf[jj]: {n-tile lo (klo,khi), n-tile hi (klo,khi)}
#pragma unroll
            for (int jj = 0; jj < 4; jj++) {
                int n = n0 + jj * 16 + rnBW;
                uint32_t adr = Bb + n * 128 + (((kk * 2 + selB) ^ (n & 7)) << 4);
                asm volatile("ldmatrix.sync.aligned.m8n8.x4.shared.b16 {%0,%1,%2,%3}, [%4];"
                    : "=r"(bf[jj][0]), "=r"(bf[jj][1]), "=r"(bf[jj][2]), "=r"(bf[jj][3])
                    : "r"(adr));
            }
#pragma unroll
            for (int i = 0; i < 4; i++)
#pragma unroll
                for (int j = 0; j < 8; j++)
                    mma_f16(acc[i][j], af[i], &bf[j >> 1][(j & 1) * 2]);
        }
        stage = (stage + 1) % WNSTAGE;
    }

    // epilogue (no bias needed for these GEMMs)
#pragma unroll
    for (int j = 0; j < 8; j++) {
        int col = col0 + n0 + j * 8 + tig * 2;
#pragma unroll
        for (int i = 0; i < 4; i++) {
            int r = row0 + m0 + i * 16 + grp;
            store2(C, (size_t)r * N + col,       alpha * acc[i][j][0], alpha * acc[i][j][1]);
            store2(C, (size_t)(r + 8) * N + col, alpha * acc[i][j][2], alpha * acc[i][j][3]);
        }
    }
}

// ------------------------- conversion / transpose kernels -------------------------
__global__ void __launch_bounds__(256)
f2h(const float* __restrict__ src, __half* __restrict__ dst, int n4)
{
    int i = blockIdx.x * blockDim.x + threadIdx.x;
    if (i < n4) {
        float4 v = reinterpret_cast<const float4*>(src)[i];
        __half2* d2 = reinterpret_cast<__half2*>(dst) + (size_t)i * 2;
        d2[0] = __floats2half2_rn(v.x, v.y);
        d2[1] = __floats2half2_rn(v.z, v.w);
    }
}

__global__ void __launch_bounds__(256)
transpose_w4(const float* __restrict__ s0, __half* __restrict__ d0,
             const float* __restrict__ s1, __half* __restrict__ d1,
             const float* __restrict__ s2, __half* __restrict__ d2,
             const float* __restrict__ s3, __half* __restrict__ d3)
{
    const float* src; __half* dst;
    switch (blockIdx.z) {
        case 0: src = s0; dst = d0; break;
        case 1: src = s1; dst = d1; break;
        case 2: src = s2; dst = d2; break;
        default: src = s3; dst = d3; break;
    }
    __shared__ float t[32][33];
    int c = blockIdx.x * 32 + threadIdx.x;
    int r = blockIdx.y * 32 + threadIdx.y;
#pragma unroll
    for (int i = 0; i < 32; i += 8)
        t[threadIdx.y + i][threadIdx.x] = src[(size_t)(r + i) * DIM + c];
    __syncthreads();
    int c2 = blockIdx.y * 32 + threadIdx.x;
    int r2 = blockIdx.x * 32 + threadIdx.y;
#pragma unroll
    for (int i = 0; i < 32; i += 8)
        dst[(size_t)(r2 + i) * DIM + c2] = __float2half_rn(t[threadIdx.x][threadIdx.y + i]);
}

// ------------------------- row softmax (half in/out, fp32 math) -------------------------
__global__ void __launch_bounds__(256)
softmax_h(__half* __restrict__ S, int n)
{
    const int row = blockIdx.x;
    const int tid = threadIdx.x;
    __half2* rp = reinterpret_cast<__half2*>(S + (size_t)row * n);

    float2 v[16];
#pragma unroll
    for (int i = 0; i < 16; i++) v[i] = __half22float2(rp[tid + i * 256]);

    float m = -INFINITY;
#pragma unroll
    for (int i = 0; i < 16; i++) m = fmaxf(m, fmaxf(v[i].x, v[i].y));
#pragma unroll
    for (int o = 16; o > 0; o >>= 1) m = fmaxf(m, __shfl_xor_sync(0xFFFFFFFFu, m, o));
    __shared__ float red[8];
    if ((tid & 31) == 0) red[tid >> 5] = m;
    __syncthreads();
    if (tid < 32) {
        float t = (tid < 8) ? red[tid] : -INFINITY;
#pragma unroll
        for (int o = 4; o > 0; o >>= 1) t = fmaxf(t, __shfl_xor_sync(0xFFFFFFFFu, t, o));
        if (tid == 0) red[0] = t;
    }
    __syncthreads();
    m = red[0];

    float s = 0.0f;
#pragma unroll
    for (int i = 0; i < 16; i++) {
        v[i].x = __expf(v[i].x - m);
        v[i].y = __expf(v[i].y - m);
        s += v[i].x + v[i].y;
    }
#pragma unroll
    for (int o = 16; o > 0; o >>= 1) s += __shfl_xor_sync(0xFFFFFFFFu, s, o);
    __syncthreads();
    if ((tid & 31) == 0) red[tid >> 5] = s;
    __syncthreads();
    if (tid < 32) {
        float t = (tid < 8) ? red[tid] : 0.0f;
#pragma unroll
        for (int o = 4; o > 0; o >>= 1) t += __shfl_xor_sync(0xFFFFFFFFu, t, o);
        if (tid == 0) red[0] = t;
    }
    __syncthreads();
    const float inv = 1.0f / red[0];

#pragma unroll
    for (int i = 0; i < 16; i++)
        rp[tid + i * 256] = __floats2half2_rn(v[i].x * inv, v[i].y * inv);
}

// ------------------------- launch -------------------------
extern "C" void kernel_launch(void* const* d_in, const int* in_sizes, int n_in,
                              void* d_out, int out_size)
{
    const float* x  = (const float*)d_in[0];
    const float* Wq = (const float*)d_in[1];
    const float* bq = (const float*)d_in[2];
    const float* Wk = (const float*)d_in[3];
    const float* bk = (const float*)d_in[4];
    const float* Wv = (const float*)d_in[5];
    const float* bv = (const float*)d_in[6];
    const float* Wo = (const float*)d_in[7];
    const float* bo = (const float*)d_in[8];
    float* out = (float*)d_out;

    __half *xh, *wqT, *wkT, *wvT, *woT, *q, *k, *vT, *t, *s;
    cudaGetSymbolAddress((void**)&xh,  g_xh);
    cudaGetSymbolAddress((void**)&wqT, g_wqT);
    cudaGetSymbolAddress((void**)&wkT, g_wkT);
    cudaGetSymbolAddress((void**)&wvT, g_wvT);
    cudaGetSymbolAddress((void**)&woT, g_woT);
    cudaGetSymbolAddress((void**)&q,   g_q);
    cudaGetSymbolAddress((void**)&k,   g_k);
    cudaGetSymbolAddress((void**)&vT,  g_vT);
    cudaGetSymbolAddress((void**)&t,   g_t);
    cudaGetSymbolAddress((void**)&s,   g_s);

    cudaFuncSetAttribute(hgemm<__half>, cudaFuncAttributeMaxDynamicSharedMemorySize, SMEM_BYTES);
    cudaFuncSetAttribute(hgemm<float>,  cudaFuncAttributeMaxDynamicSharedMemorySize, SMEM_BYTES);
    cudaFuncSetAttribute(qkv_fused,     cudaFuncAttributeMaxDynamicSharedMemorySize, SMEM_BYTES);
    cudaFuncSetAttribute(hgemm_wide<__half>, cudaFuncAttributeMaxDynamicSharedMemorySize, WSMEM_BYTES);

    const float scale = 1.0f / sqrtf((float)DIM);
    dim3 blk(256);

    f2h<<<(NTOK * DIM / 4 + 255) / 256, blk>>>(x, xh, NTOK * DIM / 4);
    {
        dim3 tb(32, 8), tg(DIM / 32, DIM / 32, 4);
        transpose_w4<<<tg, tb>>>(Wq, wqT, Wk, wkT, Wv, wvT, Wo, woT);
    }

    // fused q, k, vT
    {
        dim3 g(DIM / 128, NTOK / 128, 3);
        qkv_fused<<<g, blk, SMEM_BYTES>>>(xh, wqT, wkT, wvT, bq, bk, bv, q, k, vT);
    }

    // scores = scale * q @ k^T   (wide kernel)
    {
        dim3 g(NTOK / WBN, NTOK / WBM);      // (32, 64)
        hgemm_wide<__half><<<g, blk, WSMEM_BYTES>>>(q, k, s, NTOK, NTOK, DIM, scale);
    }

    // softmax rows in place
    softmax_h<<<NTOK, blk>>>(s, NTOK);

    // attended = attn @ v  (wide kernel; N=512 -> grid (2, 64))
    {
        dim3 g(DIM / WBN, NTOK / WBM);       // (2, 64)
        hgemm_wide<__half><<<g, blk, WSMEM_BYTES>>>(s, vT, t, NTOK, DIM, NTOK, 1.0f);
    }

    // out = attended @ Wo + bo
    {
        dim3 g(DIM / 128, NTOK / 128);
        hgemm<float><<<g, blk, SMEM_BYTES>>>(t, woT, bo, out, NTOK, DIM, DIM, 1.0f);
    }
}

// round 14
// speedup vs baseline: 1.0383x; 1.0383x over previous
#include <cuda_runtime.h>
#include <cuda_fp16.h>
#include <math.h>
#include <stdint.h>

#define NTOK 8192
#define DIM  512

// ------------------------- scratch (__device__ globals) -------------------------
__device__ __align__(256) __half g_xh [(size_t)NTOK * DIM];
__device__ __align__(256) __half g_wqT[(size_t)DIM * DIM];
__device__ __align__(256) __half g_wkT[(size_t)DIM * DIM];
__device__ __align__(256) __half g_wvT[(size_t)DIM * DIM];
__device__ __align__(256) __half g_woT[(size_t)DIM * DIM];
__device__ __align__(256) __half g_q  [(size_t)NTOK * DIM];
__device__ __align__(256) __half g_k  [(size_t)NTOK * DIM];
__device__ __align__(256) __half g_vT [(size_t)DIM * NTOK];
__device__ __align__(256) __half g_t  [(size_t)NTOK * DIM];
__device__ __align__(256) __half g_s  [(size_t)NTOK * NTOK];   // 128 MB scores/attn

// ------------------------- helpers -------------------------
__device__ __forceinline__ uint32_t smem_u32(const void* p) {
    uint32_t a;
    asm("{ .reg .u64 t; cvta.to.shared.u64 t, %1; cvt.u32.u64 %0, t; }" : "=r"(a) : "l"(p));
    return a;
}

__device__ __forceinline__ void mma_f16(float* d, const uint32_t* a, const uint32_t* b) {
    asm volatile(
        "mma.sync.aligned.m16n8k16.row.col.f32.f16.f16.f32 "
        "{%0,%1,%2,%3}, {%4,%5,%6,%7}, {%8,%9}, {%0,%1,%2,%3};"
        : "+f"(d[0]), "+f"(d[1]), "+f"(d[2]), "+f"(d[3])
        : "r"(a[0]), "r"(a[1]), "r"(a[2]), "r"(a[3]),
          "r"(b[0]), "r"(b[1]));
}

__device__ __forceinline__ void cph16(uint32_t dst, const __half* src) {
    asm volatile("cp.async.cg.shared.global [%0], [%1], 16;\n" :: "r"(dst), "l"(src));
}

__device__ __forceinline__ void store2(__half* C, size_t off, float a, float b) {
    *reinterpret_cast<__half2*>(C + off) = __floats2half2_rn(a, b);
}
__device__ __forceinline__ void store2(float* C, size_t off, float a, float b) {
    *reinterpret_cast<float2*>(C + off) = make_float2(a, b);
}

// FMA-pipe exp: exp(x) for x <= 0 (softmax args). ~2e-6 relative accuracy.
// Avoids MUFU (EX2) which is throughput-limited at 67M calls.
__device__ __forceinline__ float fexp(float x) {
    x = fmaxf(x, -80.0f);                       // keep result normal
    float y = x * 1.4426950408889634f;          // x * log2(e)
    float n = rintf(y);
    float f = y - n;                            // f in [-0.5, 0.5]
    float p =              0.0013333558f;       // 2^f Taylor (ln2 powers)
    p = fmaf(p, f, 0.0096181291f);
    p = fmaf(p, f, 0.0555041087f);
    p = fmaf(p, f, 0.2402265069f);
    p = fmaf(p, f, 0.6931471806f);
    p = fmaf(p, f, 1.0f);
    return __int_as_float(__float_as_int(p) + ((int)n << 23));
}

// ============================================================================
// 128x128 tile GEMM, 2 CTAs/SM, 3-stage cp.async, ldmatrix x4 for A and B
// ============================================================================
#define BM 128
#define BN 128
#define STAGE_BYTES (BM * 128 + BN * 128)     // 32768
#define NSTAGE 3
#define SMEM_BYTES  (NSTAGE * STAGE_BYTES + 128)

__device__ __forceinline__ void load_stage_h(const __half* __restrict__ Ag,
                                             const __half* __restrict__ Bg,
                                             int K, uint32_t Ab, uint32_t Bb, int tid)
{
#pragma unroll
    for (int i = 0; i < 4; i++) {
        int c = tid + i * 256;
        int m = c >> 3, ko = c & 7;
        cph16(Ab + m * 128 + ((ko ^ (m & 7)) << 4), Ag + (size_t)m * K + ko * 8);
    }
#pragma unroll
    for (int i = 0; i < 4; i++) {
        int c = tid + i * 256;
        int m = c >> 3, ko = c & 7;
        cph16(Bb + m * 128 + ((ko ^ (m & 7)) << 4), Bg + (size_t)m * K + ko * 8);
    }
    asm volatile("cp.async.commit_group;" ::: "memory");
}

template <typename OutT>
__device__ __forceinline__ void hgemm_core(
    const __half* __restrict__ A, const __half* __restrict__ Bt,
    const float* __restrict__ bias, OutT* __restrict__ C,
    int M, int N, int K, float alpha, bool rowbias,
    int bx, int by, uint32_t sb, int tid)
{
    const int lid = tid & 31;
    const int wid = tid >> 5;
    const int grp = lid >> 2;
    const int tig = lid & 3;
    const int m0  = (wid >> 2) * 64;
    const int n0  = (wid & 3) * 32;
    const int row0 = by * BM;
    const int col0 = bx * BN;
    const int KT = K >> 6;

    const int rrA  = (lid & 7) + ((lid >> 3) & 1) * 8;
    const int selA = (lid >> 4) & 1;
    // B x4 lane map (validated in R9): rows lo/hi 8-groups from lane>>4, chunk from lane>>3
    const int rnB2 = (lid & 7) + ((lid >> 4) & 1) * 8;
    const int selB = (lid >> 3) & 1;

    float acc[4][4][4];
#pragma unroll
    for (int i = 0; i < 4; i++)
#pragma unroll
        for (int j = 0; j < 4; j++)
#pragma unroll
            for (int e = 0; e < 4; e++) acc[i][j][e] = 0.0f;

    const __half* Arow = A  + (size_t)row0 * K;
    const __half* Brow = Bt + (size_t)col0 * K;

    load_stage_h(Arow, Brow, K, sb, sb + BM * 128, tid);
    if (KT > 1) {
        uint32_t s1 = sb + STAGE_BYTES;
        load_stage_h(Arow + 64, Brow + 64, K, s1, s1 + BM * 128, tid);
    }

    int stage = 0;
    for (int kt = 0; kt < KT; kt++) {
        if (kt + 1 < KT) asm volatile("cp.async.wait_group 1;" ::: "memory");
        else             asm volatile("cp.async.wait_group 0;" ::: "memory");
        __syncthreads();

        if (kt + 2 < KT) {
            int ls = (stage + 2) % NSTAGE;
            uint32_t Ab2 = sb + ls * STAGE_BYTES;
            load_stage_h(Arow + (kt + 2) * 64, Brow + (kt + 2) * 64, K,
                         Ab2, Ab2 + BM * 128, tid);
        }

        const uint32_t Ab = sb + stage * STAGE_BYTES;
        const uint32_t Bb = Ab + BM * 128;

#pragma unroll
        for (int kk = 0; kk < 4; kk++) {
            uint32_t af[4][4];
#pragma unroll
            for (int i = 0; i < 4; i++) {
                int m = m0 + i * 16 + rrA;
                uint32_t adr = Ab + m * 128 + (((kk * 2 + selA) ^ (m & 7)) << 4);
                asm volatile("ldmatrix.sync.aligned.m8n8.x4.shared.b16 {%0,%1,%2,%3}, [%4];"
                    : "=r"(af[i][0]), "=r"(af[i][1]), "=r"(af[i][2]), "=r"(af[i][3])
                    : "r"(adr));
            }
            uint32_t bf[2][4];   // bf[jj]: {n8-tile lo (klo,khi), n8-tile hi (klo,khi)}
#pragma unroll
            for (int jj = 0; jj < 2; jj++) {
                int n = n0 + jj * 16 + rnB2;
                uint32_t adr = Bb + n * 128 + (((kk * 2 + selB) ^ (n & 7)) << 4);
                asm volatile("ldmatrix.sync.aligned.m8n8.x4.shared.b16 {%0,%1,%2,%3}, [%4];"
                    : "=r"(bf[jj][0]), "=r"(bf[jj][1]), "=r"(bf[jj][2]), "=r"(bf[jj][3])
                    : "r"(adr));
            }
#pragma unroll
            for (int i = 0; i < 4; i++)
#pragma unroll
                for (int j = 0; j < 4; j++)
                    mma_f16(acc[i][j], af[i], &bf[j >> 1][(j & 1) * 2]);
        }
        stage = (stage + 1) % NSTAGE;
    }

#pragma unroll
    for (int j = 0; j < 4; j++) {
        int col = col0 + n0 + j * 8 + tig * 2;
        float cb0 = 0.0f, cb1 = 0.0f;
        if (bias && !rowbias) { cb0 = bias[col]; cb1 = bias[col + 1]; }
#pragma unroll
        for (int i = 0; i < 4; i++) {
            int r = row0 + m0 + i * 16 + grp;
            float rb0 = 0.0f, rb8 = 0.0f;
            if (bias && rowbias) { rb0 = bias[r]; rb8 = bias[r + 8]; }
            float f0 = alpha * acc[i][j][0] + cb0 + rb0;
            float f1 = alpha * acc[i][j][1] + cb1 + rb0;
            float f2 = alpha * acc[i][j][2] + cb0 + rb8;
            float f3 = alpha * acc[i][j][3] + cb1 + rb8;
            store2(C, (size_t)r * N + col, f0, f1);
            store2(C, (size_t)(r + 8) * N + col, f2, f3);
        }
    }
}

template <typename OutT>
__global__ void __launch_bounds__(256, 2)
hgemm(const __half* __restrict__ A, const __half* __restrict__ Bt,
      const float* __restrict__ bias, OutT* __restrict__ C,
      int M, int N, int K, float alpha)
{
    extern __shared__ char smraw[];
    uint32_t sb = (smem_u32(smraw) + 127u) & ~127u;
    hgemm_core<OutT>(A, Bt, bias, C, M, N, K, alpha, false,
                     blockIdx.x, blockIdx.y, sb, threadIdx.x);
}

__global__ void __launch_bounds__(256, 2)
qkv_fused(const __half* __restrict__ xh,
          const __half* __restrict__ wqT, const __half* __restrict__ wkT,
          const __half* __restrict__ wvT,
          const float* __restrict__ bq, const float* __restrict__ bk,
          const float* __restrict__ bv,
          __half* __restrict__ q, __half* __restrict__ k, __half* __restrict__ vT)
{
    extern __shared__ char smraw[];
    uint32_t sb = (smem_u32(smraw) + 127u) & ~127u;
    const int z = blockIdx.z;
    if (z < 2) {
        hgemm_core<__half>(xh, z ? wkT : wqT, z ? bk : bq, z ? k : q,
                           NTOK, DIM, DIM, 1.0f, false,
                           blockIdx.x, blockIdx.y, sb, threadIdx.x);
    } else {
        hgemm_core<__half>(wvT, xh, bv, vT,
                           DIM, NTOK, DIM, 1.0f, true,
                           blockIdx.y, blockIdx.x, sb, threadIdx.x);
    }
}

// ------------------------- conversion / transpose kernels -------------------------
__global__ void __launch_bounds__(256)
f2h(const float* __restrict__ src, __half* __restrict__ dst, int n4)
{
    int i = blockIdx.x * blockDim.x + threadIdx.x;
    if (i < n4) {
        float4 v = reinterpret_cast<const float4*>(src)[i];
        __half2* d2 = reinterpret_cast<__half2*>(dst) + (size_t)i * 2;
        d2[0] = __floats2half2_rn(v.x, v.y);
        d2[1] = __floats2half2_rn(v.z, v.w);
    }
}

__global__ void __launch_bounds__(256)
transpose_w4(const float* __restrict__ s0, __half* __restrict__ d0,
             const float* __restrict__ s1, __half* __restrict__ d1,
             const float* __restrict__ s2, __half* __restrict__ d2,
             const float* __restrict__ s3, __half* __restrict__ d3)
{
    const float* src; __half* dst;
    switch (blockIdx.z) {
        case 0: src = s0; dst = d0; break;
        case 1: src = s1; dst = d1; break;
        case 2: src = s2; dst = d2; break;
        default: src = s3; dst = d3; break;
    }
    __shared__ float t[32][33];
    int c = blockIdx.x * 32 + threadIdx.x;
    int r = blockIdx.y * 32 + threadIdx.y;
#pragma unroll
    for (int i = 0; i < 32; i += 8)
        t[threadIdx.y + i][threadIdx.x] = src[(size_t)(r + i) * DIM + c];
    __syncthreads();
    int c2 = blockIdx.y * 32 + threadIdx.x;
    int r2 = blockIdx.x * 32 + threadIdx.y;
#pragma unroll
    for (int i = 0; i < 32; i += 8)
        dst[(size_t)(r2 + i) * DIM + c2] = __float2half_rn(t[threadIdx.x][threadIdx.y + i]);
}

// ------------------------- row softmax (half in/out, fp32 math, FMA exp) -------------------------
__global__ void __launch_bounds__(256)
softmax_h(__half* __restrict__ S, int n)
{
    const int row = blockIdx.x;
    const int tid = threadIdx.x;
    __half2* rp = reinterpret_cast<__half2*>(S + (size_t)row * n);

    float2 v[16];
#pragma unroll
    for (int i = 0; i < 16; i++) v[i] = __half22float2(rp[tid + i * 256]);

    float m = -INFINITY;
#pragma unroll
    for (int i = 0; i < 16; i++) m = fmaxf(m, fmaxf(v[i].x, v[i].y));
#pragma unroll
    for (int o = 16; o > 0; o >>= 1) m = fmaxf(m, __shfl_xor_sync(0xFFFFFFFFu, m, o));
    __shared__ float red[8];
    if ((tid & 31) == 0) red[tid >> 5] = m;
    __syncthreads();
    if (tid < 32) {
        float t = (tid < 8) ? red[tid] : -INFINITY;
#pragma unroll
        for (int o = 4; o > 0; o >>= 1) t = fmaxf(t, __shfl_xor_sync(0xFFFFFFFFu, t, o));
        if (tid == 0) red[0] = t;
    }
    __syncthreads();
    m = red[0];

    float s = 0.0f;
#pragma unroll
    for (int i = 0; i < 16; i++) {
        v[i].x = fexp(v[i].x - m);
        v[i].y = fexp(v[i].y - m);
        s += v[i].x + v[i].y;
    }
#pragma unroll
    for (int o = 16; o > 0; o >>= 1) s += __shfl_xor_sync(0xFFFFFFFFu, s, o);
    __syncthreads();
    if ((tid & 31) == 0) red[tid >> 5] = s;
    __syncthreads();
    if (tid < 32) {
        float t = (tid < 8) ? red[tid] : 0.0f;
#pragma unroll
        for (int o = 4; o > 0; o >>= 1) t += __shfl_xor_sync(0xFFFFFFFFu, t, o);
        if (tid == 0) red[0] = t;
    }
    __syncthreads();
    const float inv = 1.0f / red[0];

#pragma unroll
    for (int i = 0; i < 16; i++)
        rp[tid + i * 256] = __floats2half2_rn(v[i].x * inv, v[i].y * inv);
}

// ------------------------- launch -------------------------
extern "C" void kernel_launch(void* const* d_in, const int* in_sizes, int n_in,
                              void* d_out, int out_size)
{
    const float* x  = (const float*)d_in[0];
    const float* Wq = (const float*)d_in[1];
    const float* bq = (const float*)d_in[2];
    const float* Wk = (const float*)d_in[3];
    const float* bk = (const float*)d_in[4];
    const float* Wv = (const float*)d_in[5];
    const float* bv = (const float*)d_in[6];
    const float* Wo = (const float*)d_in[7];
    const float* bo = (const float*)d_in[8];
    float* out = (float*)d_out;

    __half *xh, *wqT, *wkT, *wvT, *woT, *q, *k, *vT, *t, *s;
    cudaGetSymbolAddress((void**)&xh,  g_xh);
    cudaGetSymbolAddress((void**)&wqT, g_wqT);
    cudaGetSymbolAddress((void**)&wkT, g_wkT);
    cudaGetSymbolAddress((void**)&wvT, g_wvT);
    cudaGetSymbolAddress((void**)&woT, g_woT);
    cudaGetSymbolAddress((void**)&q,   g_q);
    cudaGetSymbolAddress((void**)&k,   g_k);
    cudaGetSymbolAddress((void**)&vT,  g_vT);
    cudaGetSymbolAddress((void**)&t,   g_t);
    cudaGetSymbolAddress((void**)&s,   g_s);

    cudaFuncSetAttribute(hgemm<__half>, cudaFuncAttributeMaxDynamicSharedMemorySize, SMEM_BYTES);
    cudaFuncSetAttribute(hgemm<float>,  cudaFuncAttributeMaxDynamicSharedMemorySize, SMEM_BYTES);
    cudaFuncSetAttribute(qkv_fused,     cudaFuncAttributeMaxDynamicSharedMemorySize, SMEM_BYTES);

    const float scale = 1.0f / sqrtf((float)DIM);
    dim3 blk(256);

    f2h<<<(NTOK * DIM / 4 + 255) / 256, blk>>>(x, xh, NTOK * DIM / 4);
    {
        dim3 tb(32, 8), tg(DIM / 32, DIM / 32, 4);
        transpose_w4<<<tg, tb>>>(Wq, wqT, Wk, wkT, Wv, wvT, Wo, woT);
    }

    // fused q, k, vT
    {
        dim3 g(DIM / 128, NTOK / 128, 3);
        qkv_fused<<<g, blk, SMEM_BYTES>>>(xh, wqT, wkT, wvT, bq, bk, bv, q, k, vT);
    }

    // scores = scale * q @ k^T
    {
        dim3 g(NTOK / 128, NTOK / 128);      // (64, 64)
        hgemm<__half><<<g, blk, SMEM_BYTES>>>(q, k, nullptr, s, NTOK, NTOK, DIM, scale);
    }

    // softmax rows in place (FMA-pipe exp)
    softmax_h<<<NTOK, blk>>>(s, NTOK);

    // attended = attn @ v  (= attn @ vT^T)
    {
        dim3 g(DIM / 128, NTOK / 128);       // (4, 64)
        hgemm<__half><<<g, blk, SMEM_BYTES>>>(s, vT, nullptr, t, NTOK, DIM, NTOK, 1.0f);
    }

    // out = attended @ Wo + bo
    {
        dim3 g(DIM / 128, NTOK / 128);
        hgemm<float><<<g, blk, SMEM_BYTES>>>(t, woT, bo, out, NTOK, DIM, DIM, 1.0f);
    }
}

// round 16
// speedup vs baseline: 1.0939x; 1.0536x over previous
#include <cuda_runtime.h>
#include <cuda_fp16.h>
#include <math.h>
#include <stdint.h>

#define NTOK 8192
#define DIM  512

// ------------------------- scratch (__device__ globals) -------------------------
__device__ __align__(256) __half g_xh [(size_t)NTOK * DIM];
__device__ __align__(256) __half g_wqT[(size_t)DIM * DIM];
__device__ __align__(256) __half g_wkT[(size_t)DIM * DIM];
__device__ __align__(256) __half g_wvT[(size_t)DIM * DIM];
__device__ __align__(256) __half g_woT[(size_t)DIM * DIM];
__device__ __align__(256) __half g_q  [(size_t)NTOK * DIM];
__device__ __align__(256) __half g_k  [(size_t)NTOK * DIM];
__device__ __align__(256) __half g_vT [(size_t)DIM * NTOK];
__device__ __align__(256) __half g_t  [(size_t)NTOK * DIM];
__device__ __align__(256) __half g_s  [(size_t)NTOK * NTOK];   // 128 MB scores/attn

// ------------------------- helpers -------------------------
__device__ __forceinline__ uint32_t smem_u32(const void* p) {
    uint32_t a;
    asm("{ .reg .u64 t; cvta.to.shared.u64 t, %1; cvt.u32.u64 %0, t; }" : "=r"(a) : "l"(p));
    return a;
}

__device__ __forceinline__ void mma_f16(float* d, const uint32_t* a, const uint32_t* b) {
    asm volatile(
        "mma.sync.aligned.m16n8k16.row.col.f32.f16.f16.f32 "
        "{%0,%1,%2,%3}, {%4,%5,%6,%7}, {%8,%9}, {%0,%1,%2,%3};"
        : "+f"(d[0]), "+f"(d[1]), "+f"(d[2]), "+f"(d[3])
        : "r"(a[0]), "r"(a[1]), "r"(a[2]), "r"(a[3]),
          "r"(b[0]), "r"(b[1]));
}

__device__ __forceinline__ void cph16(uint32_t dst, const __half* src) {
    asm volatile("cp.async.cg.shared.global [%0], [%1], 16;\n" :: "r"(dst), "l"(src));
}

// mbarrier primitives (PTX sm_80+/sm_90+, legal on base sm_103)
#define MBAR_INIT(a, c)  asm volatile("mbarrier.init.shared.b64 [%0], %1;" :: "r"(a), "r"(c) : "memory")
#define MBAR_ARRIVE(a)   asm volatile("mbarrier.arrive.shared.b64 _, [%0];" :: "r"(a) : "memory")
#define CPASYNC_MBAR_ARRIVE(a) \
    asm volatile("cp.async.mbarrier.arrive.noinc.shared.b64 [%0];" :: "r"(a) : "memory")

__device__ __forceinline__ void mbar_wait(uint32_t mbar, uint32_t parity) {
    uint32_t done;
    asm volatile(
        "{\n\t.reg .pred p;\n\t"
        "mbarrier.try_wait.parity.acquire.cta.shared::cta.b64 p, [%1], %2;\n\t"
        "selp.b32 %0, 1, 0, p;\n\t}"
        : "=r"(done) : "r"(mbar), "r"(parity) : "memory");
    if (!done) {
        asm volatile(
            "{\n\t.reg .pred P1;\n\t"
            "WL_%=:\n\t"
            "mbarrier.try_wait.parity.acquire.cta.shared::cta.b64 P1, [%0], %1, 0x989680;\n\t"
            "@P1 bra.uni WD_%=;\n\t"
            "bra.uni WL_%=;\n\t"
            "WD_%=:\n\t}"
            :: "r"(mbar), "r"(parity) : "memory");
    }
}

__device__ __forceinline__ void store2(__half* C, size_t off, float a, float b) {
    *reinterpret_cast<__half2*>(C + off) = __floats2half2_rn(a, b);
}
__device__ __forceinline__ void store2(float* C, size_t off, float a, float b) {
    *reinterpret_cast<float2*>(C + off) = make_float2(a, b);
}

// FMA-pipe exp: exp(x) for x <= 0 (softmax args). ~2e-6 relative accuracy.
__device__ __forceinline__ float fexp(float x) {
    x = fmaxf(x, -80.0f);
    float y = x * 1.4426950408889634f;
    float n = rintf(y);
    float f = y - n;
    float p =              0.0013333558f;
    p = fmaf(p, f, 0.0096181291f);
    p = fmaf(p, f, 0.0555041087f);
    p = fmaf(p, f, 0.2402265069f);
    p = fmaf(p, f, 0.6931471806f);
    p = fmaf(p, f, 1.0f);
    return __int_as_float(__float_as_int(p) + ((int)n << 23));
}

// ============================================================================
// 128x128 tile GEMM, 2 CTAs/SM, 3-stage mbarrier async pipeline (no mainloop
// __syncthreads -> no LDSM/HMMA convoy), ldmatrix x4(A)/x2(B) fragments.
// ============================================================================
#define BM 128
#define BN 128
#define STAGE_BYTES (BM * 128 + BN * 128)     // 32768
#define NSTAGE 3
// stages + alignment slack + 6 mbarriers (3 x {full,empty} x 8B)
#define SMEM_BYTES  (NSTAGE * STAGE_BYTES + 256)

// issue cp.async for one 64-K chunk (no commit_group; tracked via mbarrier)
__device__ __forceinline__ void load_stage_h(const __half* __restrict__ Ag,
                                             const __half* __restrict__ Bg,
                                             int K, uint32_t Ab, uint32_t Bb, int tid)
{
#pragma unroll
    for (int i = 0; i < 4; i++) {
        int c = tid + i * 256;
        int m = c >> 3, ko = c & 7;
        cph16(Ab + m * 128 + ((ko ^ (m & 7)) << 4), Ag + (size_t)m * K + ko * 8);
    }
#pragma unroll
    for (int i = 0; i < 4; i++) {
        int c = tid + i * 256;
        int m = c >> 3, ko = c & 7;
        cph16(Bb + m * 128 + ((ko ^ (m & 7)) << 4), Bg + (size_t)m * K + ko * 8);
    }
}

template <typename OutT>
__device__ __forceinline__ void hgemm_core(
    const __half* __restrict__ A, const __half* __restrict__ Bt,
    const float* __restrict__ bias, OutT* __restrict__ C,
    int M, int N, int K, float alpha, bool rowbias,
    int bx, int by, uint32_t sb, int tid)
{
    const int lid = tid & 31;
    const int wid = tid >> 5;
    const int grp = lid >> 2;
    const int tig = lid & 3;
    const int m0  = (wid >> 2) * 64;
    const int n0  = (wid & 3) * 32;
    const int row0 = by * BM;
    const int col0 = bx * BN;
    const int KT = K >> 6;

    const int rrA  = (lid & 7) + ((lid >> 3) & 1) * 8;
    const int selA = (lid >> 4) & 1;
    const int rnB  = lid & 7;
    const int selB = (lid >> 3) & 1;

    // mbarriers: full[s] at mb + s*16, empty[s] at mb + s*16 + 8
    const uint32_t mb = sb + NSTAGE * STAGE_BYTES;
    if (tid == 0) {
#pragma unroll
        for (int s = 0; s < NSTAGE; s++) {
            MBAR_INIT(mb + s * 16,     256u);   // full
            MBAR_INIT(mb + s * 16 + 8, 256u);   // empty
        }
    }
    __syncthreads();                 // init visible before any arrive/wait

    float acc[4][4][4];
#pragma unroll
    for (int i = 0; i < 4; i++)
#pragma unroll
        for (int j = 0; j < 4; j++)
#pragma unroll
            for (int e = 0; e < 4; e++) acc[i][j][e] = 0.0f;

    const __half* Arow = A  + (size_t)row0 * K;
    const __half* Brow = Bt + (size_t)col0 * K;

    // cursors
    int pstage = 0, pphase = 1;      // producer: first empty-wait passes
    int cstage = 0, cphase = 0;      // consumer

    // prologue: fill stages 0 and 1
#pragma unroll
    for (int f = 0; f < 2; f++) {
        if (f < KT) {
            mbar_wait(mb + pstage * 16 + 8, (uint32_t)pphase);
            uint32_t Ab = sb + pstage * STAGE_BYTES;
            load_stage_h(Arow + f * 64, Brow + f * 64, K, Ab, Ab + BM * 128, tid);
            CPASYNC_MBAR_ARRIVE(mb + pstage * 16);
            if (++pstage == NSTAGE) { pstage = 0; pphase ^= 1; }
        }
    }

    for (int kt = 0; kt < KT; kt++) {
        // prefetch chunk kt+2 into the free stage
        if (kt + 2 < KT) {
            mbar_wait(mb + pstage * 16 + 8, (uint32_t)pphase);
            uint32_t Ab2 = sb + pstage * STAGE_BYTES;
            load_stage_h(Arow + (kt + 2) * 64, Brow + (kt + 2) * 64, K,
                         Ab2, Ab2 + BM * 128, tid);
            CPASYNC_MBAR_ARRIVE(mb + pstage * 16);
            if (++pstage == NSTAGE) { pstage = 0; pphase ^= 1; }
        }

        // wait for this chunk's data
        mbar_wait(mb + cstage * 16, (uint32_t)cphase);

        const uint32_t Ab = sb + cstage * STAGE_BYTES;
        const uint32_t Bb = Ab + BM * 128;

#pragma unroll
        for (int kk = 0; kk < 4; kk++) {
            uint32_t af[4][4];
#pragma unroll
            for (int i = 0; i < 4; i++) {
                int m = m0 + i * 16 + rrA;
                uint32_t adr = Ab + m * 128 + (((kk * 2 + selA) ^ (m & 7)) << 4);
                asm volatile("ldmatrix.sync.aligned.m8n8.x4.shared.b16 {%0,%1,%2,%3}, [%4];"
                    : "=r"(af[i][0]), "=r"(af[i][1]), "=r"(af[i][2]), "=r"(af[i][3])
                    : "r"(adr));
            }
            uint32_t bf[4][2];
#pragma unroll
            for (int j = 0; j < 4; j++) {
                int n = n0 + j * 8 + rnB;
                uint32_t adr = Bb + n * 128 + (((kk * 2 + selB) ^ (n & 7)) << 4);
                asm volatile("ldmatrix.sync.aligned.m8n8.x2.shared.b16 {%0,%1}, [%2];"
                    : "=r"(bf[j][0]), "=r"(bf[j][1])
                    : "r"(adr));
            }
#pragma unroll
            for (int i = 0; i < 4; i++)
#pragma unroll
                for (int j = 0; j < 4; j++)
                    mma_f16(acc[i][j], af[i], bf[j]);
        }

        // done reading this stage
        MBAR_ARRIVE(mb + cstage * 16 + 8);
        if (++cstage == NSTAGE) { cstage = 0; cphase ^= 1; }
    }

    // ---- epilogue (per-thread acc; no barrier needed) ----
#pragma unroll
    for (int j = 0; j < 4; j++) {
        int col = col0 + n0 + j * 8 + tig * 2;
        float cb0 = 0.0f, cb1 = 0.0f;
        if (bias && !rowbias) { cb0 = bias[col]; cb1 = bias[col + 1]; }
#pragma unroll
        for (int i = 0; i < 4; i++) {
            int r = row0 + m0 + i * 16 + grp;
            float rb0 = 0.0f, rb8 = 0.0f;
            if (bias && rowbias) { rb0 = bias[r]; rb8 = bias[r + 8]; }
            float f0 = alpha * acc[i][j][0] + cb0 + rb0;
            float f1 = alpha * acc[i][j][1] + cb1 + rb0;
            float f2 = alpha * acc[i][j][2] + cb0 + rb8;
            float f3 = alpha * acc[i][j][3] + cb1 + rb8;
            store2(C, (size_t)r * N + col, f0, f1);
            store2(C, (size_t)(r + 8) * N + col, f2, f3);
        }
    }
}

template <typename OutT>
__global__ void __launch_bounds__(256, 2)
hgemm(const __half* __restrict__ A, const __half* __restrict__ Bt,
      const float* __restrict__ bias, OutT* __restrict__ C,
      int M, int N, int K, float alpha)
{
    extern __shared__ char smraw[];
    uint32_t sb = (smem_u32(smraw) + 127u) & ~127u;
    hgemm_core<OutT>(A, Bt, bias, C, M, N, K, alpha, false,
                     blockIdx.x, blockIdx.y, sb, threadIdx.x);
}

__global__ void __launch_bounds__(256, 2)
qkv_fused(const __half* __restrict__ xh,
          const __half* __restrict__ wqT, const __half* __restrict__ wkT,
          const __half* __restrict__ wvT,
          const float* __restrict__ bq, const float* __restrict__ bk,
          const float* __restrict__ bv,
          __half* __restrict__ q, __half* __restrict__ k, __half* __restrict__ vT)
{
    extern __shared__ char smraw[];
    uint32_t sb = (smem_u32(smraw) + 127u) & ~127u;
    const int z = blockIdx.z;
    if (z < 2) {
        hgemm_core<__half>(xh, z ? wkT : wqT, z ? bk : bq, z ? k : q,
                           NTOK, DIM, DIM, 1.0f, false,
                           blockIdx.x, blockIdx.y, sb, threadIdx.x);
    } else {
        hgemm_core<__half>(wvT, xh, bv, vT,
                           DIM, NTOK, DIM, 1.0f, true,
                           blockIdx.y, blockIdx.x, sb, threadIdx.x);
    }
}

// ------------------------- conversion / transpose kernels -------------------------
__global__ void __launch_bounds__(256)
f2h(const float* __restrict__ src, __half* __restrict__ dst, int n4)
{
    int i = blockIdx.x * blockDim.x + threadIdx.x;
    if (i < n4) {
        float4 v = reinterpret_cast<const float4*>(src)[i];
        __half2* d2 = reinterpret_cast<__half2*>(dst) + (size_t)i * 2;
        d2[0] = __floats2half2_rn(v.x, v.y);
        d2[1] = __floats2half2_rn(v.z, v.w);
    }
}

__global__ void __launch_bounds__(256)
transpose_w4(const float* __restrict__ s0, __half* __restrict__ d0,
             const float* __restrict__ s1, __half* __restrict__ d1,
             const float* __restrict__ s2, __half* __restrict__ d2,
             const float* __restrict__ s3, __half* __restrict__ d3)
{
    const float* src; __half* dst;
    switch (blockIdx.z) {
        case 0: src = s0; dst = d0; break;
        case 1: src = s1; dst = d1; break;
        case 2: src = s2; dst = d2; break;
        default: src = s3; dst = d3; break;
    }
    __shared__ float t[32][33];
    int c = blockIdx.x * 32 + threadIdx.x;
    int r = blockIdx.y * 32 + threadIdx.y;
#pragma unroll
    for (int i = 0; i < 32; i += 8)
        t[threadIdx.y + i][threadIdx.x] = src[(size_t)(r + i) * DIM + c];
    __syncthreads();
    int c2 = blockIdx.y * 32 + threadIdx.x;
    int r2 = blockIdx.x * 32 + threadIdx.y;
#pragma unroll
    for (int i = 0; i < 32; i += 8)
        dst[(size_t)(r2 + i) * DIM + c2] = __float2half_rn(t[threadIdx.x][threadIdx.y + i]);
}

// ------------------------- row softmax (half in/out, fp32 math, FMA exp) -------------------------
__global__ void __launch_bounds__(256)
softmax_h(__half* __restrict__ S, int n)
{
    const int row = blockIdx.x;
    const int tid = threadIdx.x;
    __half2* rp = reinterpret_cast<__half2*>(S + (size_t)row * n);

    float2 v[16];
#pragma unroll
    for (int i = 0; i < 16; i++) v[i] = __half22float2(rp[tid + i * 256]);

    float m = -INFINITY;
#pragma unroll
    for (int i = 0; i < 16; i++) m = fmaxf(m, fmaxf(v[i].x, v[i].y));
#pragma unroll
    for (int o = 16; o > 0; o >>= 1) m = fmaxf(m, __shfl_xor_sync(0xFFFFFFFFu, m, o));
    __shared__ float red[8];
    if ((tid & 31) == 0) red[tid >> 5] = m;
    __syncthreads();
    if (tid < 32) {
        float t = (tid < 8) ? red[tid] : -INFINITY;
#pragma unroll
        for (int o = 4; o > 0; o >>= 1) t = fmaxf(t, __shfl_xor_sync(0xFFFFFFFFu, t, o));
        if (tid == 0) red[0] = t;
    }
    __syncthreads();
    m = red[0];

    float s = 0.0f;
#pragma unroll
    for (int i = 0; i < 16; i++) {
        v[i].x = fexp(v[i].x - m);
        v[i].y = fexp(v[i].y - m);
        s += v[i].x + v[i].y;
    }
#pragma unroll
    for (int o = 16; o > 0; o >>= 1) s += __shfl_xor_sync(0xFFFFFFFFu, s, o);
    __syncthreads();
    if ((tid & 31) == 0) red[tid >> 5] = s;
    __syncthreads();
    if (tid < 32) {
        float t = (tid < 8) ? red[tid] : 0.0f;
#pragma unroll
        for (int o = 4; o > 0; o >>= 1) t += __shfl_xor_sync(0xFFFFFFFFu, t, o);
        if (tid == 0) red[0] = t;
    }
    __syncthreads();
    const float inv = 1.0f / red[0];

#pragma unroll
    for (int i = 0; i < 16; i++)
        rp[tid + i * 256] = __floats2half2_rn(v[i].x * inv, v[i].y * inv);
}

// ------------------------- launch -------------------------
extern "C" void kernel_launch(void* const* d_in, const int* in_sizes, int n_in,
                              void* d_out, int out_size)
{
    const float* x  = (const float*)d_in[0];
    const float* Wq = (const float*)d_in[1];
    const float* bq = (const float*)d_in[2];
    const float* Wk = (const float*)d_in[3];
    const float* bk = (const float*)d_in[4];
    const float* Wv = (const float*)d_in[5];
    const float* bv = (const float*)d_in[6];
    const float* Wo = (const float*)d_in[7];
    const float* bo = (const float*)d_in[8];
    float* out = (float*)d_out;

    __half *xh, *wqT, *wkT, *wvT, *woT, *q, *k, *vT, *t, *s;
    cudaGetSymbolAddress((void**)&xh,  g_xh);
    cudaGetSymbolAddress((void**)&wqT, g_wqT);
    cudaGetSymbolAddress((void**)&wkT, g_wkT);
    cudaGetSymbolAddress((void**)&wvT, g_wvT);
    cudaGetSymbolAddress((void**)&woT, g_woT);
    cudaGetSymbolAddress((void**)&q,   g_q);
    cudaGetSymbolAddress((void**)&k,   g_k);
    cudaGetSymbolAddress((void**)&vT,  g_vT);
    cudaGetSymbolAddress((void**)&t,   g_t);
    cudaGetSymbolAddress((void**)&s,   g_s);

    cudaFuncSetAttribute(hgemm<__half>, cudaFuncAttributeMaxDynamicSharedMemorySize, SMEM_BYTES);
    cudaFuncSetAttribute(hgemm<float>,  cudaFuncAttributeMaxDynamicSharedMemorySize, SMEM_BYTES);
    cudaFuncSetAttribute(qkv_fused,     cudaFuncAttributeMaxDynamicSharedMemorySize, SMEM_BYTES);

    const float scale = 1.0f / sqrtf((float)DIM);
    dim3 blk(256);

    f2h<<<(NTOK * DIM / 4 + 255) / 256, blk>>>(x, xh, NTOK * DIM / 4);
    {
        dim3 tb(32, 8), tg(DIM / 32, DIM / 32, 4);
        transpose_w4<<<tg, tb>>>(Wq, wqT, Wk, wkT, Wv, wvT, Wo, woT);
    }

    // fused q, k, vT
    {
        dim3 g(DIM / 128, NTOK / 128, 3);
        qkv_fused<<<g, blk, SMEM_BYTES>>>(xh, wqT, wkT, wvT, bq, bk, bv, q, k, vT);
    }

    // scores = scale * q @ k^T
    {
        dim3 g(NTOK / 128, NTOK / 128);      // (64, 64)
        hgemm<__half><<<g, blk, SMEM_BYTES>>>(q, k, nullptr, s, NTOK, NTOK, DIM, scale);
    }

    // softmax rows in place (FMA-pipe exp)
    softmax_h<<<NTOK, blk>>>(s, NTOK);

    // attended = attn @ v  (= attn @ vT^T)
    {
        dim3 g(DIM / 128, NTOK / 128);       // (4, 64)
        hgemm<__half><<<g, blk, SMEM_BYTES>>>(s, vT, nullptr, t, NTOK, DIM, NTOK, 1.0f);
    }

    // out = attended @ Wo + bo
    {
        dim3 g(DIM / 128, NTOK / 128);
        hgemm<float><<<g, blk, SMEM_BYTES>>>(t, woT, bo, out, NTOK, DIM, DIM, 1.0f);
    }
}